// round 17
// baseline (speedup 1.0000x reference)
#include <cuda_runtime.h>
#include <cstdint>

// WaveNet dilated causal conv stack.
// 2-CTA cluster per batch element; fused conv+io; ping-pong h in SMEM.
// 2 positions/thread (float2), NTH=544 one-shot bodies.
// Register-tail halo pushes (R14). Single change vs R14: weights read
// directly from gmem via uniform __ldg (no constant bank, no pack kernel,
// no memcpy node — single-node graph).
// Split points: M0=1088; M_i = 1086 + 2^(i+1).

#define NTH 544
#define LBUF 2176
#define FRAME 128
#define TFULL 4096

typedef unsigned long long u64;

__device__ __forceinline__ uint32_t s2u(const void* p) {
    return (uint32_t)__cvta_generic_to_shared(p);
}
__device__ __forceinline__ uint32_t mapa_peer(uint32_t a, uint32_t peer) {
    uint32_t r;
    asm volatile("mapa.shared::cluster.u32 %0, %1, %2;" : "=r"(r) : "r"(a), "r"(peer));
    return r;
}
__device__ __forceinline__ void st_dsm64(uint32_t a, float x, float y) {
    u64 v = (u64)__float_as_uint(x) | ((u64)__float_as_uint(y) << 32);
    asm volatile("st.shared::cluster.b64 [%0], %1;" :: "r"(a), "l"(v) : "memory");
}
#define CS() do { asm volatile("barrier.cluster.arrive.aligned;" ::: "memory"); \
                  asm volatile("barrier.cluster.wait.aligned;" ::: "memory"); } while(0)

extern __shared__ float smem[];

__global__ __launch_bounds__(NTH) __cluster_dims__(2, 1, 1)
void wavenet_kernel(const float* __restrict__ X,
                    const float* __restrict__ C0,   // (3,1,8)   [w*8+co]
                    const float* __restrict__ CK,   // (9,3,8,8) [((i-1)*3+w)*64+ci*8+co]
                    const float* __restrict__ CB,   // (10,8)
                    const float* __restrict__ IOK,  // (9,1,8,8) [i*64+ci*8+co]
                    const float* __restrict__ IOB,  // (9,8)
                    const float* __restrict__ MIX,  // (80,)
                    const float* __restrict__ MIXB, // (1,)
                    float* __restrict__ out)
{
    float* xb   = smem;              // LBUF
    float* hA   = smem + LBUF;       // 8*LBUF   h[c*LBUF + l]
    float* hB   = smem + 9 * LBUF;   // 8*LBUF
    float* oacc = smem + 17 * LBUF;  // FRAME

    const int tid = threadIdx.x;
    uint32_t rank;
    asm("mov.u32 %0, %%cluster_ctarank;" : "=r"(rank));
    const uint32_t peer = rank ^ 1u;
    const int b = blockIdx.x >> 1;
    const float* x = X + b * TFULL + (TFULL - LBUF);

    for (int l = tid; l < LBUF; l += NTH) xb[l] = x[l];
    if (rank && tid < FRAME) oacc[tid] = __ldg(MIXB);
    __syncthreads();

    // ---- layer 0 (pairs) -> hA; producer pushes its boundary pair from regs ----
    {
        const int M = 1088;
        const int lo = rank ? M : 2;
        const int hi = rank ? LBUF : M;
        const uint32_t pb = mapa_peer(s2u(hA), peer);
        for (int l = lo + 2 * tid; l < hi; l += 2 * NTH) {
            float2 A = *(const float2*)&xb[l - 2];
            float2 B = *(const float2*)&xb[l];
            float acc0[8], acc1[8];
#pragma unroll
            for (int co = 0; co < 8; co++) {
                float w0 = __ldg(C0 + co), w1 = __ldg(C0 + 8 + co), w2 = __ldg(C0 + 16 + co);
                float bb = __ldg(CB + co);
                acc0[co] = fmaxf(fmaf(B.x, w2, fmaf(A.y, w1, fmaf(A.x, w0, bb))), 0.0f);
                acc1[co] = fmaxf(fmaf(B.y, w2, fmaf(B.x, w1, fmaf(A.y, w0, bb))), 0.0f);
            }
            if (l >= LBUF - FRAME) {
                float m0 = 0.0f, m1 = 0.0f;
#pragma unroll
                for (int co = 0; co < 8; co++) {
                    float mw = __ldg(MIX + co);
                    m0 = fmaf(acc0[co], mw, m0); m1 = fmaf(acc1[co], mw, m1);
                }
                oacc[l - (LBUF - FRAME)]     += m0;
                oacc[l - (LBUF - FRAME) + 1] += m1;
            }
            float o0[8], o1[8];
#pragma unroll
            for (int co = 0; co < 8; co++) {
                float bb = __ldg(IOB + co);
                float a0 = bb + B.x, a1 = bb + B.y;
#pragma unroll
                for (int ci = 0; ci < 8; ci++) {
                    float wk = __ldg(IOK + ci * 8 + co);
                    a0 = fmaf(acc0[ci], wk, a0); a1 = fmaf(acc1[ci], wk, a1);
                }
                o0[co] = a0; o1[co] = a1;
                *(float2*)(hA + co * LBUF + l) = make_float2(a0, a1);
            }
            if (l == (rank ? 1088 : 1086)) {
#pragma unroll
                for (int co = 0; co < 8; co++)
                    st_dsm64(pb + (uint32_t)(co * LBUF + l) * 4u, o0[co], o1[co]);
            }
        }
    }
    CS();

    // ---- layers 1..8 (pairs), ping-pong, register-tail push halos ----
#pragma unroll
    for (int i = 1; i < 9; i++) {
        const int d = 1 << i;
        const int S = (4 << i) - 2;            // 2*(2^{i+1}-1)
        const int M = 1086 + (2 << i);
        const int W = 2 << i;                  // halo width for layer i+1
        float* cur = (i & 1) ? hA : hB;
        float* nxt = (i & 1) ? hB : hA;
        const uint32_t pb = mapa_peer(s2u(nxt), peer);

        const int lo = rank ? M : S;
        const int hi = rank ? LBUF : M;
        for (int l = lo + 2 * tid; l < hi; l += 2 * NTH) {
            float acc0[8], acc1[8], hl0[8], hl1[8];
#pragma unroll
            for (int co = 0; co < 8; co++) { acc0[co] = __ldg(CB + i * 8 + co); acc1[co] = acc0[co]; }
#pragma unroll
            for (int w = 0; w < 3; w++) {
                const int off = (2 - w) * d;
#pragma unroll
                for (int ci = 0; ci < 8; ci++) {
                    float2 v = *(const float2*)(cur + ci * LBUF + (l - off));
                    if (w == 2) { hl0[ci] = v.x; hl1[ci] = v.y; }
#pragma unroll
                    for (int co = 0; co < 8; co++) {
                        float wk = __ldg(CK + (((i - 1) * 3 + w) * 8 + ci) * 8 + co);
                        acc0[co] = fmaf(v.x, wk, acc0[co]); acc1[co] = fmaf(v.y, wk, acc1[co]);
                    }
                }
            }
#pragma unroll
            for (int co = 0; co < 8; co++) { acc0[co] = fmaxf(acc0[co], 0.0f); acc1[co] = fmaxf(acc1[co], 0.0f); }
            if (l >= LBUF - FRAME) {
                float m0 = 0.0f, m1 = 0.0f;
#pragma unroll
                for (int co = 0; co < 8; co++) {
                    float mw = __ldg(MIX + i * 8 + co);
                    m0 = fmaf(acc0[co], mw, m0); m1 = fmaf(acc1[co], mw, m1);
                }
                oacc[l - (LBUF - FRAME)]     += m0;
                oacc[l - (LBUF - FRAME) + 1] += m1;
            }
            float o0[8], o1[8];
#pragma unroll
            for (int co = 0; co < 8; co++) {
                float bb = __ldg(IOB + i * 8 + co);
                float a0 = bb + hl0[co], a1 = bb + hl1[co];
#pragma unroll
                for (int ci = 0; ci < 8; ci++) {
                    float wk = __ldg(IOK + (i * 8 + ci) * 8 + co);
                    a0 = fmaf(acc0[ci], wk, a0); a1 = fmaf(acc1[ci], wk, a1);
                }
                o0[co] = a0; o1[co] = a1;
                *(float2*)(nxt + co * LBUF + l) = make_float2(a0, a1);
            }
            bool push;
            if (i == 8)   // layer 9 runs on rank1 only; rank0 pushes its strips
                push = rank ? false : ((l >= 1024 && l < 1152) || (l >= 1536 && l < 1598));
            else
                push = rank ? (l >= M && l < M + W) : (l >= M - W && l < M);
            if (push) {
#pragma unroll
                for (int co = 0; co < 8; co++)
                    st_dsm64(pb + (uint32_t)(co * LBUF + l) * 4u, o0[co], o1[co]);
            }
        }
        CS();
    }

    // ---- layer 9 (rank1 only, pairs): reads own hA, last FRAME positions ----
    if (rank) {
        const int i = 9, d = 512;
        for (int l = (LBUF - FRAME) + 2 * tid; l < LBUF; l += 2 * NTH) {
            float acc0[8], acc1[8];
#pragma unroll
            for (int co = 0; co < 8; co++) { acc0[co] = __ldg(CB + i * 8 + co); acc1[co] = acc0[co]; }
#pragma unroll
            for (int w = 0; w < 3; w++) {
                const int off = (2 - w) * d;
#pragma unroll
                for (int ci = 0; ci < 8; ci++) {
                    float2 v = *(const float2*)(hA + ci * LBUF + (l - off));
#pragma unroll
                    for (int co = 0; co < 8; co++) {
                        float wk = __ldg(CK + (((i - 1) * 3 + w) * 8 + ci) * 8 + co);
                        acc0[co] = fmaf(v.x, wk, acc0[co]); acc1[co] = fmaf(v.y, wk, acc1[co]);
                    }
                }
            }
            float m0 = 0.0f, m1 = 0.0f;
#pragma unroll
            for (int co = 0; co < 8; co++) {
                float mw = __ldg(MIX + i * 8 + co);
                m0 = fmaf(fmaxf(acc0[co], 0.0f), mw, m0);
                m1 = fmaf(fmaxf(acc1[co], 0.0f), mw, m1);
            }
            oacc[l - (LBUF - FRAME)]     += m0;
            oacc[l - (LBUF - FRAME) + 1] += m1;
        }
        __syncthreads();
        if (tid < FRAME) out[b * FRAME + tid] = oacc[tid];
    }
}

static const int SMEM_BYTES = (17 * LBUF + FRAME) * (int)sizeof(float);

extern "C" void kernel_launch(void* const* d_in, const int* in_sizes, int n_in,
                              void* d_out, int out_size) {
    (void)in_sizes; (void)n_in; (void)out_size;
    cudaFuncSetAttribute(wavenet_kernel, cudaFuncAttributeMaxDynamicSharedMemorySize, SMEM_BYTES);
    wavenet_kernel<<<128, NTH, SMEM_BYTES>>>(
        (const float*)d_in[0], (const float*)d_in[1], (const float*)d_in[2],
        (const float*)d_in[3], (const float*)d_in[4], (const float*)d_in[5],
        (const float*)d_in[6], (const float*)d_in[7], (float*)d_out);
}